// round 16
// baseline (speedup 1.0000x reference)
#include <cuda_runtime.h>

// Fused bilinear 2x up -> leaky_relu(0.01) -> bilinear 0.5x down == 3x3 stencil.
// x, out: (16, 128, 128, 128) fp32 NHWC.
//
// R14 = R13 (42.4us: V-first factorization, FFMA-imm corner, prologue L2
// prefetch of the strip, 3 CTAs/80 regs) + in-loop L1 prefetch one column
// ahead (4x prefetch.global.L1 per iter, no regs/smem/sync). In-loop LDGs
// then hit L1 (~39cyc) instead of L2 (~250cyc). R12 proved hiding the
// latency lifts issue 40->70%; this is the near-free way to buy it.

constexpr int H   = 128;
constexpr int W   = 128;
constexpr int C4  = 32;    // 128 channels / 4
constexpr int WC4 = W * C4;
constexpr int STRIP = 8;   // output columns per thread

__device__ __forceinline__ void prefetch_l2(const void* p) {
    asm volatile("prefetch.global.L2 [%0];" :: "l"(p));
}
__device__ __forceinline__ void prefetch_l1(const void* p) {
    asm volatile("prefetch.global.L1 [%0];" :: "l"(p));
}

// vertical stage: 4 x-rows -> 4 upsampled V-rows (t-sharing, FFMA-imm)
__device__ __forceinline__ void vquad(const float4& xa, const float4& xb,
                                      const float4& xc, const float4& xd,
                                      float4& V0, float4& V1, float4& V2, float4& V3) {
    {
        float t0 = 0.75f * xb.x, t1 = 0.75f * xc.x;
        V0.x = fmaf(xa.x, 0.25f, t0); V1.x = fmaf(xc.x, 0.25f, t0);
        V2.x = fmaf(xb.x, 0.25f, t1); V3.x = fmaf(xd.x, 0.25f, t1);
    }
    {
        float t0 = 0.75f * xb.y, t1 = 0.75f * xc.y;
        V0.y = fmaf(xa.y, 0.25f, t0); V1.y = fmaf(xc.y, 0.25f, t0);
        V2.y = fmaf(xb.y, 0.25f, t1); V3.y = fmaf(xd.y, 0.25f, t1);
    }
    {
        float t0 = 0.75f * xb.z, t1 = 0.75f * xc.z;
        V0.z = fmaf(xa.z, 0.25f, t0); V1.z = fmaf(xc.z, 0.25f, t0);
        V2.z = fmaf(xb.z, 0.25f, t1); V3.z = fmaf(xd.z, 0.25f, t1);
    }
    {
        float t0 = 0.75f * xb.w, t1 = 0.75f * xc.w;
        V0.w = fmaf(xa.w, 0.25f, t0); V1.w = fmaf(xc.w, 0.25f, t0);
        V2.w = fmaf(xb.w, 0.25f, t1); V3.w = fmaf(xd.w, 0.25f, t1);
    }
}

// horizontal stage on a V row: L = .25a+.75b ; R = .75b+.25c
__device__ __forceinline__ void hlerp(const float4& a, const float4& b, const float4& c,
                                      float4& L, float4& R) {
    float tx = 0.75f * b.x, ty = 0.75f * b.y, tz = 0.75f * b.z, tw = 0.75f * b.w;
    L = make_float4(fmaf(a.x, 0.25f, tx), fmaf(a.y, 0.25f, ty),
                    fmaf(a.z, 0.25f, tz), fmaf(a.w, 0.25f, tw));
    R = make_float4(fmaf(c.x, 0.25f, tx), fmaf(c.y, 0.25f, ty),
                    fmaf(c.z, 0.25f, tz), fmaf(c.w, 0.25f, tw));
}

// out = 0.25*sum_k leaky(u_k) == 0.12625*sum(u) + 0.12375*sum(|u|)
// one FMUL-imm + 7 FFMA-imm per channel; abs folds into FFMA modifiers
__device__ __forceinline__ float corner1(float u00, float u01, float u10, float u11) {
    float r = u00 * 0.12625f;
    r = fmaf(u01, 0.12625f, r);
    r = fmaf(u10, 0.12625f, r);
    r = fmaf(u11, 0.12625f, r);
    r = fmaf(fabsf(u00), 0.12375f, r);
    r = fmaf(fabsf(u01), 0.12375f, r);
    r = fmaf(fabsf(u10), 0.12375f, r);
    r = fmaf(fabsf(u11), 0.12375f, r);
    return r;
}

__device__ __forceinline__ float4 corner_sum(const float4& u00, const float4& u01,
                                             const float4& u10, const float4& u11) {
    return make_float4(corner1(u00.x, u01.x, u10.x, u11.x),
                       corner1(u00.y, u01.y, u10.y, u11.y),
                       corner1(u00.z, u01.z, u10.z, u11.z),
                       corner1(u00.w, u01.w, u10.w, u11.w));
}

__global__ __launch_bounds__(256, 3)
void activation_filter_kernel(const float4* __restrict__ x, float4* __restrict__ out) {
    const int r0 = 2 * blockIdx.x;     // output row pair (r0, r0+1)
    const int half = blockIdx.y;       // width half (0: cols 0..63, 1: 64..127)
    const int b  = blockIdx.z;
    const int tid = threadIdx.x;
    const int c4    = tid & 31;
    const int strip = tid >> 5;        // 0..7, warp-uniform
    const int j0    = half * 64 + strip * STRIP;

    const int im = (r0 > 0)         ? r0 - 1 : 0;      // row above r0 (clamped)
    const int iq = (r0 + 1 < H - 1) ? r0 + 2 : H - 1;  // row below r1 (clamped)

    const int img   = b * (H * WC4);
    const int basec = j0 * C4 + c4;
    const float4* __restrict__ pa = x + img + im * WC4 + basec;   // row im
    const float4* __restrict__ pb = x + img + r0 * WC4 + basec;   // rows r0 (+WC4 -> r1)
    const float4* __restrict__ pd = x + img + iq * WC4 + basec;   // row iq
    float4* __restrict__ po = out + img + r0 * WC4 + basec;       // rows r0 (+WC4 -> r1)

    // prologue: direct loads for cols j0-1 (clamped, warp-uniform) and j0
    const int offA = (j0 > 0) ? -C4 : 0;
    float4 xa0 = pa[offA], xb0 = pb[offA], xc0 = pb[offA + WC4], xd0 = pd[offA];
    float4 ya0 = pa[0],    yb0 = pb[0],    yc0 = pb[WC4],        yd0 = pd[0];

    // L2-prefetch the rest of the strip (cols +1..+7 all in-bounds: j0max+7=127)
    // in the shadow of the prologue loads; L1-prefetch col +1 (used in iter 0).
    #pragma unroll
    for (int t = 1; t <= STRIP - 1; ++t) {
        prefetch_l2(pa + t * C4);
        prefetch_l2(pb + t * C4);
        prefetch_l2(pb + t * C4 + WC4);
        prefetch_l2(pd + t * C4);
    }
    prefetch_l1(pa + C4);
    prefetch_l1(pb + C4);
    prefetch_l1(pb + C4 + WC4);
    prefetch_l1(pd + C4);

    float4 Vp0, Vp1, Vp2, Vp3, Vc0, Vc1, Vc2, Vc3;
    vquad(xa0, xb0, xc0, xd0, Vp0, Vp1, Vp2, Vp3);
    vquad(ya0, yb0, yc0, yd0, Vc0, Vc1, Vc2, Vc3);

    #pragma unroll
    for (int s = 0; s < STRIP - 1; ++s) {
        // all loads first: 4 independent LDG.128 (col j+1, L1-warm)
        float4 xa = pa[C4];
        float4 xb = pb[C4];
        float4 xc = pb[C4 + WC4];
        float4 xd = pd[C4];

        // L1-prefetch col j+2 for the next iteration (warp-uniform guard)
        if (j0 + s + 2 < W) {
            prefetch_l1(pa + 2 * C4);
            prefetch_l1(pb + 2 * C4);
            prefetch_l1(pb + 2 * C4 + WC4);
            prefetch_l1(pd + 2 * C4);
        }

        float4 Vn0, Vn1, Vn2, Vn3;
        vquad(xa, xb, xc, xd, Vn0, Vn1, Vn2, Vn3);

        {   // output row r0 (up-rows V0, V1)
            float4 uL0, uR0, uL1, uR1;
            hlerp(Vp0, Vc0, Vn0, uL0, uR0);
            hlerp(Vp1, Vc1, Vn1, uL1, uR1);
            __stcs(po, corner_sum(uL0, uR0, uL1, uR1));
        }
        {   // output row r1 (up-rows V2, V3)
            float4 uL2, uR2, uL3, uR3;
            hlerp(Vp2, Vc2, Vn2, uL2, uR2);
            hlerp(Vp3, Vc3, Vn3, uL3, uR3);
            __stcs(po + WC4, corner_sum(uL2, uR2, uL3, uR3));
        }

        // slide V window
        Vp0 = Vc0; Vp1 = Vc1; Vp2 = Vc2; Vp3 = Vc3;
        Vc0 = Vn0; Vc1 = Vn1; Vc2 = Vn2; Vc3 = Vn3;
        pa += C4; pb += C4; pd += C4; po += C4;
    }

    // final column: only the rightmost strip clamps (warp-uniform); V is
    // linear so clamped x columns imply Vn = Vc exactly.
    {
        float4 Vn0, Vn1, Vn2, Vn3;
        if (j0 + STRIP < W) {
            float4 xa = pa[C4], xb = pb[C4], xc = pb[C4 + WC4], xd = pd[C4];
            vquad(xa, xb, xc, xd, Vn0, Vn1, Vn2, Vn3);
        } else {
            Vn0 = Vc0; Vn1 = Vc1; Vn2 = Vc2; Vn3 = Vc3;
        }
        {
            float4 uL0, uR0, uL1, uR1;
            hlerp(Vp0, Vc0, Vn0, uL0, uR0);
            hlerp(Vp1, Vc1, Vn1, uL1, uR1);
            __stcs(po, corner_sum(uL0, uR0, uL1, uR1));
        }
        {
            float4 uL2, uR2, uL3, uR3;
            hlerp(Vp2, Vc2, Vn2, uL2, uR2);
            hlerp(Vp3, Vc3, Vn3, uL3, uR3);
            __stcs(po + WC4, corner_sum(uL2, uR2, uL3, uR3));
        }
    }
}

extern "C" void kernel_launch(void* const* d_in, const int* in_sizes, int n_in,
                              void* d_out, int out_size) {
    const float4* x = (const float4*)d_in[0];
    float4* out = (float4*)d_out;
    dim3 grid(H / 2, 2, 16);   // (row pair, width half, batch) = 2048 blocks
    activation_filter_kernel<<<grid, 256>>>(x, out);
}